// round 7
// baseline (speedup 1.0000x reference)
#include <cuda_runtime.h>

// LIF recurrence, B=64 T=256 U=1024 fp32.
// Time-segmented x8 (SEG=32, warmup W=16: tau^16 ~ 2e-10 << fp32 ulp -> exact spikes).
// float4 lanes: LDG.128/STG.128 halve memory-instruction count.
// __ldcg: bypass L1 (zero reuse stream); __stcs: evict-first stores keep input L2-resident.
// 131072 threads (~28 warps/SM) - the occupancy level R4 proved sufficient.

#define T_LEN 256
#define U4    256             // U/4 float4 lanes
#define SEG   32
#define W     16
#define NSEG  (T_LEN / SEG)   // 8
#define D     4               // t-steps per chunk
#define NWCH  (W / D)         // 4 warmup chunks
#define NCH   (NWCH + SEG / D) // 12 chunks total

__global__ __launch_bounds__(128, 8)
void lif_kernel(const float4* __restrict__ in, float4* __restrict__ out) {
    const int gid = blockIdx.x * blockDim.x + threadIdx.x;   // 0..131071
    const int u4  = gid & (U4 - 1);
    const int rs  = gid >> 8;
    const int seg = rs & (NSEG - 1);
    const int b   = rs >> 3;

    const float4* __restrict__ ip = in  + (size_t)b * T_LEN * U4 + u4;
    float4*       __restrict__ op = out + (size_t)b * T_LEN * U4 + u4;

    const int t0 = seg * SEG;
    const int ts = (seg == 0) ? 0 : (t0 - W);   // warmup start (seg0's warmup discarded)

    float vx = 0.f, vy = 0.f, vz = 0.f, vw = 0.f;
    float4 A[D], B[D];

    // chunk k start time: warmup chunks from ts, main chunks from t0
    #define CH_T(k) (((k) < NWCH) ? (ts + (k) * D) : (t0 + ((k) - NWCH) * D))

    #define LOADCH(buf, tstart) do {                                    \
        _Pragma("unroll")                                               \
        for (int i = 0; i < D; ++i)                                     \
            (buf)[i] = __ldcg(&ip[(size_t)((tstart) + i) * U4]);        \
    } while (0)

    #define PROCCH(buf, k) do {                                         \
        _Pragma("unroll")                                               \
        for (int i = 0; i < D; ++i) {                                   \
            float4 x = (buf)[i];                                        \
            vx = fmaf(0.25f, vx, 0.75f * x.x);                          \
            vy = fmaf(0.25f, vy, 0.75f * x.y);                          \
            vz = fmaf(0.25f, vz, 0.75f * x.z);                          \
            vw = fmaf(0.25f, vw, 0.75f * x.w);                          \
            float sx = (vx > 1.0f) ? 1.0f : 0.0f;                       \
            float sy = (vy > 1.0f) ? 1.0f : 0.0f;                       \
            float sz = (vz > 1.0f) ? 1.0f : 0.0f;                       \
            float sw = (vw > 1.0f) ? 1.0f : 0.0f;                       \
            vx -= sx; vy -= sy; vz -= sz; vw -= sw;                     \
            if ((k) >= NWCH)                                            \
                __stcs(&op[(size_t)(CH_T(k) + i) * U4],                 \
                       make_float4(sx, sy, sz, sw));                    \
        }                                                               \
        if ((k) == NWCH - 1 && seg == 0) { vx = vy = vz = vw = 0.f; }   \
    } while (0)

    // prime ping-pong
    LOADCH(A, CH_T(0));
    LOADCH(B, CH_T(1));

    #pragma unroll
    for (int k = 0; k < NCH; k += 2) {
        PROCCH(A, k);
        if (k + 2 < NCH) LOADCH(A, CH_T(k + 2));
        if (k + 1 < NCH) PROCCH(B, k + 1);
        if (k + 3 < NCH) LOADCH(B, CH_T(k + 3));
    }

    #undef CH_T
    #undef LOADCH
    #undef PROCCH
}

extern "C" void kernel_launch(void* const* d_in, const int* in_sizes, int n_in,
                              void* d_out, int out_size) {
    const float4* in  = (const float4*)d_in[0];
    float4*       out = (float4*)d_out;

    const int total   = in_sizes[0];                 // B*T*U
    const int lanes   = total / 4 / T_LEN;           // B*U4 = 16384
    const int threads = lanes * NSEG;                // 131072

    const int block = 128;
    const int grid  = threads / block;               // 1024
    lif_kernel<<<grid, block>>>(in, out);
}

// round 8
// speedup vs baseline: 1.0920x; 1.0920x over previous
#include <cuda_runtime.h>

// LIF recurrence, B=64 T=256 U=1024 fp32. R4 structure (champion) with flipped
// cache policy: output (written every graph replay, never device-read) kept
// L2-resident via plain stores; input streamed with __ldcs (evict-first) so it
// doesn't evict the output. Steady-state DRAM traffic -> read-only ~82MB.
// Time-segmented x4: SEG=64, warmup W=24 (tau^24 ~ 3e-15 << fp32 ulp -> exact).

#define T_LEN 256
#define U2    512            // U/2 float2 lanes
#define SEG   64
#define W     24
#define NSEG  (T_LEN / SEG)  // 4
#define D     8              // t-steps per chunk
#define NWCH  (W / D)        // 3 warmup chunks
#define NCH   (NWCH + SEG / D)  // 11 chunks total

__global__ __launch_bounds__(128, 7)
void lif_kernel(const float2* __restrict__ in, float2* __restrict__ out) {
    const int gid = blockIdx.x * blockDim.x + threadIdx.x;   // 0..131071
    const int u2  = gid & (U2 - 1);
    const int rs  = gid >> 9;
    const int seg = rs & (NSEG - 1);
    const int b   = rs >> 2;

    const float2* __restrict__ ip = in  + (size_t)b * T_LEN * U2 + u2;
    float2*       __restrict__ op = out + (size_t)b * T_LEN * U2 + u2;

    const int t0 = seg * SEG;
    const int ts = (seg == 0) ? 0 : (t0 - W);   // warmup start (seg0's warmup discarded)

    float vx = 0.f, vy = 0.f;
    float2 A[D], B[D];

    // chunk k start time: warmup chunks from ts, main chunks from t0
    #define CH_T(k) (((k) < NWCH) ? (ts + (k) * D) : (t0 + ((k) - NWCH) * D))

    #define LOADCH(buf, tstart) do {                                   \
        _Pragma("unroll")                                              \
        for (int i = 0; i < D; ++i)                                    \
            (buf)[i] = __ldcs(&ip[(size_t)((tstart) + i) * U2]);       \
    } while (0)

    #define PROCCH(buf, k) do {                                        \
        _Pragma("unroll")                                              \
        for (int i = 0; i < D; ++i) {                                  \
            float2 x = (buf)[i];                                       \
            vx = fmaf(0.25f, vx, 0.75f * x.x);                         \
            vy = fmaf(0.25f, vy, 0.75f * x.y);                         \
            float sx = (vx > 1.0f) ? 1.0f : 0.0f;                      \
            float sy = (vy > 1.0f) ? 1.0f : 0.0f;                      \
            vx -= sx; vy -= sy;                                        \
            if ((k) >= NWCH)                                           \
                op[(size_t)(CH_T(k) + i) * U2] = make_float2(sx, sy);  \
        }                                                              \
        if ((k) == NWCH - 1 && seg == 0) { vx = 0.f; vy = 0.f; }       \
    } while (0)

    // prime ping-pong
    LOADCH(A, CH_T(0));
    LOADCH(B, CH_T(1));

    #pragma unroll
    for (int k = 0; k < NCH; k += 2) {
        PROCCH(A, k);
        if (k + 2 < NCH) LOADCH(A, CH_T(k + 2));
        if (k + 1 < NCH) PROCCH(B, k + 1);
        if (k + 3 < NCH) LOADCH(B, CH_T(k + 3));
    }

    #undef CH_T
    #undef LOADCH
    #undef PROCCH
}

extern "C" void kernel_launch(void* const* d_in, const int* in_sizes, int n_in,
                              void* d_out, int out_size) {
    const float2* in  = (const float2*)d_in[0];
    float2*       out = (float2*)d_out;

    const int total   = in_sizes[0];                 // B*T*U
    const int lanes   = total / 2 / T_LEN;           // B*U2 = 32768
    const int threads = lanes * NSEG;                // 131072

    const int block = 128;
    const int grid  = threads / block;               // 1024
    lif_kernel<<<grid, block>>>(in, out);
}